// round 3
// baseline (speedup 1.0000x reference)
#include <cuda_runtime.h>
#include <cuda_bf16.h>
#include <math.h>
#include <float.h>

// ---------------- Problem constants ----------------
#define N_ANCH   25200
#define ROW_LEN  117          // 4 box + 1 obj + 80 cls + 32 coef
#define NC       80
#define NM       32
#define TOPK     1024
#define MAX_DET  300
#define IMG      640
#define PROTO_HW 160
#define PROTO_PX (PROTO_HW*PROTO_HW)   // 25600
#define CONF_T   0.25f
#define IOU_T    0.45f
#define MAX_WH   7680.0f

#define CAND_CAP 4096

// Output layout (all float32, concatenated):
// masks_f [300*640*640], masks_bool [300*640*640], fb [300*4], fs [300], fcls [300]
#define PLANE      ((long long)MAX_DET * IMG * IMG)        // 122,880,000
#define OF_BOOL    (PLANE)
#define OF_FB      (2*PLANE)
#define OF_FS      (2*PLANE + MAX_DET*4)
#define OF_FCLS    (2*PLANE + MAX_DET*4 + MAX_DET)

// ---------------- Device scratch ----------------
__device__ unsigned            g_hist[65536];
__device__ unsigned            g_ss[N_ANCH];           // sortable score bits
__device__ unsigned            g_thresh;
__device__ int                 g_ccount;
__device__ unsigned long long  g_cand[CAND_CAP];
__device__ float               g_topscore[TOPK];
__device__ float               g_box[TOPK*4];          // xyxy
__device__ float               g_nbox[TOPK*4];         // xyxy + cls*MAX_WH
__device__ int                 g_cls[TOPK];
__device__ int                 g_oidx[TOPK];
__device__ unsigned            g_sup[TOPK*32];         // suppression bitmask
__device__ float               g_fcoef[MAX_DET*NM];
__device__ float               g_fb[MAX_DET*4];
__device__ int                 g_fvalid[MAX_DET];
__device__ float               g_m[MAX_DET*PROTO_PX];  // sigmoid mask logits @160x160

// ---------------- helpers ----------------
__device__ __forceinline__ unsigned f2s(float f) {
    unsigned u = __float_as_uint(f);
    return (u & 0x80000000u) ? ~u : (u | 0x80000000u);
}
__device__ __forceinline__ float s2f(unsigned s) {
    unsigned u = (s & 0x80000000u) ? (s & 0x7FFFFFFFu) : ~s;
    return __uint_as_float(u);
}

// ---------------- K0: init ----------------
__global__ void k_init() {
    int i = blockIdx.x*blockDim.x + threadIdx.x;
    if (i < 65536) g_hist[i] = 0;
    if (i == 0) g_ccount = 0;
}

// ---------------- K1: per-anchor scores + histogram ----------------
__global__ void k_score(const float* __restrict__ pred) {
    int i = blockIdx.x*blockDim.x + threadIdx.x;
    if (i >= N_ANCH) return;
    const float* r = pred + (long long)i*ROW_LEN;
    float obj = r[4];
    float best = -1e30f;
    #pragma unroll 8
    for (int c = 0; c < NC; c++) {
        float v = r[5+c] * obj;
        if (v > best) best = v;
    }
    bool valid = (obj > CONF_T) && (best > CONF_T);
    float score = valid ? best : -1.0f;
    unsigned s = f2s(score);
    g_ss[i] = s;
    if (valid) atomicAdd(&g_hist[s >> 16], 1u);
}

// ---------------- K2: find threshold bucket ----------------
__global__ void k_thresh() {
    __shared__ unsigned psum[256];
    int tid = threadIdx.x;
    int hi = 65535 - tid*256;
    unsigned s = 0;
    for (int k = 0; k < 256; k++) s += g_hist[hi - k];
    psum[tid] = s;
    __syncthreads();
    if (tid == 0) {
        unsigned total = 0;
        for (int t = 0; t < 256; t++) total += psum[t];
        unsigned target = total < TOPK ? total : TOPK;
        if (target == 0) { g_thresh = 65536u; return; }
        unsigned cum = 0; int t = 0;
        while (cum + psum[t] < target) { cum += psum[t]; t++; }
        int b = 65535 - t*256;
        while (true) { cum += g_hist[b]; if (cum >= target) break; b--; }
        g_thresh = (unsigned)b;
    }
}

// ---------------- K3: gather candidates ----------------
__global__ void k_gather() {
    int i = blockIdx.x*blockDim.x + threadIdx.x;
    if (i >= N_ANCH) return;
    unsigned s = g_ss[i];
    if ((s >> 16) >= g_thresh) {
        int pos = atomicAdd(&g_ccount, 1);
        if (pos < CAND_CAP) {
            g_cand[pos] = ((unsigned long long)s << 32) | (unsigned)(N_ANCH - 1 - i);
        }
    }
}

// ---------------- K4: bitonic sort + extract top-1024 ----------------
__global__ void k_sort(const float* __restrict__ pred) {
    __shared__ unsigned long long sm[CAND_CAP];   // 32 KB
    int tid = threadIdx.x;
    int cnt = g_ccount; if (cnt > CAND_CAP) cnt = CAND_CAP;
    for (int i = tid; i < CAND_CAP; i += 1024) sm[i] = (i < cnt) ? g_cand[i] : 0ULL;
    __syncthreads();
    for (unsigned k = 2; k <= CAND_CAP; k <<= 1) {
        for (unsigned j = k >> 1; j > 0; j >>= 1) {
            for (unsigned i = tid; i < CAND_CAP; i += 1024) {
                unsigned ixj = i ^ j;
                if (ixj > i) {
                    unsigned long long a = sm[i], b = sm[ixj];
                    bool descRun = (i & k) == 0;
                    bool doSwap = descRun ? (a < b) : (a > b);
                    if (doSwap) { sm[i] = b; sm[ixj] = a; }
                }
            }
            __syncthreads();
        }
    }
    // extract
    if (tid < TOPK) {
        unsigned long long key = sm[tid];
        float score; int idx;
        if (key == 0ULL) { score = -1.0f; idx = 0; }
        else {
            score = s2f((unsigned)(key >> 32));
            idx = N_ANCH - 1 - (int)(unsigned)(key & 0xFFFFFFFFu);
        }
        g_topscore[tid] = score;
        g_oidx[tid] = idx;
        const float* r = pred + (long long)idx*ROW_LEN;
        float cx = r[0], cy = r[1], w = r[2], h = r[3];
        float x1 = cx - w*0.5f, y1 = cy - h*0.5f, x2 = cx + w*0.5f, y2 = cy + h*0.5f;
        float obj = r[4];
        float best = -1e30f; int bj = 0;
        for (int c = 0; c < NC; c++) {
            float v = r[5+c]*obj;
            if (v > best) { best = v; bj = c; }
        }
        g_cls[tid] = bj;
        g_box[tid*4+0] = x1; g_box[tid*4+1] = y1; g_box[tid*4+2] = x2; g_box[tid*4+3] = y2;
        float off = (float)bj * MAX_WH;
        g_nbox[tid*4+0] = x1+off; g_nbox[tid*4+1] = y1+off; g_nbox[tid*4+2] = x2+off; g_nbox[tid*4+3] = y2+off;
    }
}

// ---------------- K5: suppression matrix (1024x1024 bits) ----------------
__global__ void k_sup() {
    int id = blockIdx.x*blockDim.x + threadIdx.x;   // 32768 words
    if (id >= TOPK*32) return;
    int i = id >> 5;
    int w = id & 31;
    float ax1 = g_nbox[i*4+0], ay1 = g_nbox[i*4+1], ax2 = g_nbox[i*4+2], ay2 = g_nbox[i*4+3];
    float a1 = (ax2-ax1)*(ay2-ay1);
    unsigned bits = 0;
    #pragma unroll 4
    for (int b = 0; b < 32; b++) {
        int j = w*32 + b;
        float bx1 = g_nbox[j*4+0], by1 = g_nbox[j*4+1], bx2 = g_nbox[j*4+2], by2 = g_nbox[j*4+3];
        float ix = fmaxf(fminf(ax2,bx2) - fmaxf(ax1,bx1), 0.f);
        float iy = fmaxf(fminf(ay2,by2) - fmaxf(ay1,by1), 0.f);
        float inter = ix*iy;
        float a2 = (bx2-bx1)*(by2-by1);
        float iou = inter / (a1 + a2 - inter + 1e-7f);
        if (iou > IOU_T) bits |= (1u << b);
    }
    g_sup[id] = bits;
}

// ---------------- K6: NMS resolve + finalize dets ----------------
__global__ void k_nms_final(const float* __restrict__ pred, float* __restrict__ out) {
    __shared__ unsigned kw[32];
    __shared__ int s_det[MAX_DET];
    __shared__ int s_ndet;
    int tid = threadIdx.x;
    if (tid < 32) {
        int lane = tid;
        kw[lane] = 0;
        __syncwarp();
        for (int c = 0; c < 32; c++) {
            int i = c*32 + lane;
            bool valid = g_topscore[i] > CONF_T;
            bool pre = false;
            const unsigned* srow = &g_sup[i*32];
            for (int w = 0; w < c; w++) pre |= (kw[w] & srow[w]) != 0;
            unsigned sup_self = srow[c];
            unsigned lowmask = (lane == 0) ? 0u : ((1u << lane) - 1u);
            unsigned ck = 0;
            #pragma unroll 1
            for (int b = 0; b < 32; b++) {
                unsigned my = 0;
                if (lane == b) {
                    bool sup = pre || ((ck & sup_self & lowmask) != 0);
                    my = (valid && !sup) ? 1u : 0u;
                }
                unsigned nb = __shfl_sync(0xffffffffu, my, b);
                ck |= nb << b;
            }
            if (lane == 0) kw[c] = ck;
            __syncwarp();
        }
        if (lane == 0) {
            int n = 0;
            for (int c = 0; c < 32 && n < MAX_DET; c++) {
                unsigned wv = kw[c];
                while (wv && n < MAX_DET) {
                    int b = __ffs(wv) - 1;
                    wv &= wv - 1;
                    s_det[n++] = c*32 + b;
                }
            }
            s_ndet = n;
        }
    }
    __syncthreads();
    int n = s_ndet;
    for (int d = tid; d < MAX_DET; d += blockDim.x) {
        if (d < n) {
            int ci = s_det[d];
            int oi = g_oidx[ci];
            float fs = g_topscore[ci];
            float b0 = g_box[ci*4+0], b1 = g_box[ci*4+1], b2 = g_box[ci*4+2], b3 = g_box[ci*4+3];
            int cls = g_cls[ci];
            g_fvalid[d] = 1;
            g_fb[d*4+0]=b0; g_fb[d*4+1]=b1; g_fb[d*4+2]=b2; g_fb[d*4+3]=b3;
            out[OF_FB + d*4+0]=b0; out[OF_FB + d*4+1]=b1; out[OF_FB + d*4+2]=b2; out[OF_FB + d*4+3]=b3;
            out[OF_FS + d] = fs;
            out[OF_FCLS + d] = (float)cls;
            const float* r = pred + (long long)oi*ROW_LEN + 5 + NC;
            for (int k = 0; k < NM; k++) g_fcoef[d*NM+k] = r[k];
        } else {
            g_fvalid[d] = 0;
            g_fb[d*4+0]=0.f; g_fb[d*4+1]=0.f; g_fb[d*4+2]=0.f; g_fb[d*4+3]=0.f;
            out[OF_FB + d*4+0]=0.f; out[OF_FB + d*4+1]=0.f; out[OF_FB + d*4+2]=0.f; out[OF_FB + d*4+3]=0.f;
            out[OF_FS + d] = 0.f;
            out[OF_FCLS + d] = -1.0f;
            for (int k = 0; k < NM; k++) g_fcoef[d*NM+k] = 0.f;
        }
    }
}

// ---------------- K7: mask GEMM + sigmoid (300x32 @ 32x25600) ----------------
#define GD 16   // dets per block
__global__ void k_gemm(const float* __restrict__ protos) {
    __shared__ float sp[NM][256];
    __shared__ float fc[GD][NM];
    int tid = threadIdx.x;
    int p0 = blockIdx.x * 256;
    int d0 = blockIdx.y * GD;
    for (int idx = tid; idx < GD*NM; idx += 256) {
        int dd = idx / NM, k = idx % NM;
        int d = d0 + dd;
        fc[dd][k] = (d < MAX_DET) ? g_fcoef[d*NM + k] : 0.f;
    }
    #pragma unroll 8
    for (int k = 0; k < NM; k++) sp[k][tid] = protos[(long long)k*PROTO_PX + p0 + tid];
    __syncthreads();
    int p = p0 + tid;
    #pragma unroll 4
    for (int dd = 0; dd < GD; dd++) {
        int d = d0 + dd;
        if (d >= MAX_DET) break;
        float acc = 0.f;
        #pragma unroll
        for (int k = 0; k < NM; k++) acc = fmaf(fc[dd][k], sp[k][tid], acc);
        g_m[(long long)d*PROTO_PX + p] = 1.0f / (1.0f + expf(-acc));
    }
}

// ---------------- K8: resize + crop + write masks ----------------
__global__ void k_resize(float* __restrict__ out) {
    int d = blockIdx.y;
    int row = blockIdx.x;
    int t = threadIdx.x;              // 160 threads
    __shared__ float rb[PROTO_HW];

    bool val = g_fvalid[d] != 0;
    float x1 = g_fb[d*4+0], y1 = g_fb[d*4+1], x2 = g_fb[d*4+2], y2 = g_fb[d*4+3];
    float rowf = (float)row;
    bool rowin = val && (rowf >= y1) && (rowf < y2);

    long long base = (long long)d * (IMG*IMG) + (long long)row * IMG;
    if (rowin) {
        float ys = (rowf + 0.5f)*0.25f - 0.5f;
        ys = fminf(fmaxf(ys, 0.f), (float)(PROTO_HW-1));
        int yA = (int)ys;
        float fy = ys - (float)yA;
        int yB = yA + 1; if (yB > PROTO_HW-1) yB = PROTO_HW-1;
        const float* mrow = &g_m[(long long)d*PROTO_PX];
        rb[t] = mrow[yA*PROTO_HW + t]*(1.0f - fy) + mrow[yB*PROTO_HW + t]*fy;
        __syncthreads();
        int c0 = t*4;
        float4 vf, vb;
        float* pf = (float*)&vf;
        float* pb = (float*)&vb;
        #pragma unroll
        for (int k = 0; k < 4; k++) {
            int col = c0 + k;
            float colf = (float)col;
            float xs = (colf + 0.5f)*0.25f - 0.5f;
            xs = fminf(fmaxf(xs, 0.f), (float)(PROTO_HW-1));
            int xA = (int)xs;
            float fx = xs - (float)xA;
            int xB = xA + 1; if (xB > PROTO_HW-1) xB = PROTO_HW-1;
            float v = rb[xA]*(1.0f - fx) + rb[xB]*fx;
            bool inx = (colf >= x1) && (colf < x2);
            float o = inx ? v : 0.f;
            pf[k] = o;
            pb[k] = (o > 0.5f) ? 1.0f : 0.0f;
        }
        *(float4*)(out + base + c0) = vf;
        *(float4*)(out + OF_BOOL + base + c0) = vb;
    } else {
        float4 z = make_float4(0.f, 0.f, 0.f, 0.f);
        int c0 = t*4;
        *(float4*)(out + base + c0) = z;
        *(float4*)(out + OF_BOOL + base + c0) = z;
    }
}

// ---------------- launch ----------------
extern "C" void kernel_launch(void* const* d_in, const int* in_sizes, int n_in,
                              void* d_out, int out_size) {
    const float* pred   = (const float*)d_in[0];
    const float* protos = (const float*)d_in[1];
    float* out = (float*)d_out;

    k_init<<<(65536+255)/256, 256>>>();
    k_score<<<(N_ANCH+255)/256, 256>>>(pred);
    k_thresh<<<1, 256>>>();
    k_gather<<<(N_ANCH+255)/256, 256>>>();
    k_sort<<<1, 1024>>>(pred);
    k_sup<<<(TOPK*32+255)/256, 256>>>();
    k_nms_final<<<1, 256>>>(pred, out);
    k_gemm<<<dim3(PROTO_PX/256, (MAX_DET+GD-1)/GD), 256>>>(protos);
    k_resize<<<dim3(IMG, MAX_DET), PROTO_HW>>>(out);
}